// round 2
// baseline (speedup 1.0000x reference)
#include <cuda_runtime.h>
#include <math.h>

#define BSZ   8192
#define DD    512
#define UNITS 256
#define NRIM  6
#define TOPK  4
#define NIH   2
#define IKS   64
#define IVS   400
#define NCH   4
#define CKS   32
#define CVS   100

#define BF (BSZ*NRIM*UNITS)   // 8192*1536

// ---------------- scratch (device globals; no allocations allowed) ------------
__device__ float g_kx  [BSZ*128];      // x@key_W + key_b
__device__ float g_vx  [BSZ*800];      // x@value_W + value_b
__device__ float g_q   [BSZ*NRIM*128]; // hs @ query_W[n]
__device__ float g_mask[BSZ*NRIM];
__device__ float g_rnn [BSZ*NRIM*IVS];
__device__ float g_pre [BSZ*NRIM*1024];
__device__ float g_hnew[BSZ*NRIM*UNITS];
__device__ float g_ck  [BSZ*NRIM*128];
__device__ float g_cv  [BSZ*NRIM*400];
__device__ float g_cq  [BSZ*NRIM*128];
__device__ float g_ctx [BSZ*NRIM*400];
__device__ float g_hcm [BSZ*NRIM*UNITS];

// ---------------- generic fp32 GEMM: C[M x N] = A[M x K] * W[K x N] (+bias)(+C) ---
// M fixed = 8192 (grid.y = 64), 128x128 tile, BK=8, 256 threads, 8x8 micro-tile.
// Batched over blockIdx.z with element strides sA/sW/sC.
__global__ void __launch_bounds__(256) gemm128(
    const float* __restrict__ A, const float* __restrict__ W,
    const float* __restrict__ bias, float* __restrict__ C,
    int N, int Kd, int lda, int ldw, int ldc,
    long sA, long sW, long sC, int accum)
{
    A += (long)blockIdx.z * sA;
    W += (long)blockIdx.z * sW;
    C += (long)blockIdx.z * sC;

    __shared__ float As[8][128];
    __shared__ float Ws[8][128];

    const int tid = threadIdx.x;
    const int m0  = blockIdx.y * 128;
    const int n0  = blockIdx.x * 128;

    const int aRow = tid >> 1;          // 0..127
    const int aK   = (tid & 1) * 4;     // 0 or 4
    const int wK   = tid >> 5;          // 0..7
    const int wC   = (tid & 31) * 4;    // 0..124
    const int ty   = tid >> 4;          // 0..15
    const int tx   = tid & 15;          // 0..15

    float acc[8][8];
#pragma unroll
    for (int i = 0; i < 8; i++)
#pragma unroll
        for (int j = 0; j < 8; j++) acc[i][j] = 0.f;

    const float* Aptr = A + (long)(m0 + aRow) * lda + aK;

    for (int k0 = 0; k0 < Kd; k0 += 8) {
        // A tile (transposed into As[k][m]); all A shapes are K%8==0, 16B aligned
        float4 av = *(const float4*)(Aptr + k0);
        As[aK + 0][aRow] = av.x;
        As[aK + 1][aRow] = av.y;
        As[aK + 2][aRow] = av.z;
        As[aK + 3][aRow] = av.w;

        // W tile with N guard
        {
            const int col = n0 + wC;
            const float* wp = W + (long)(k0 + wK) * ldw;
            if (col + 3 < N) {
                *(float4*)&Ws[wK][wC] = *(const float4*)(wp + col);
            } else {
#pragma unroll
                for (int j = 0; j < 4; j++)
                    Ws[wK][wC + j] = (col + j < N) ? wp[col + j] : 0.f;
            }
        }
        __syncthreads();

#pragma unroll
        for (int kk = 0; kk < 8; kk++) {
            float a[8], bq[8];
            *(float4*)(a)      = *(const float4*)&As[kk][ty * 8];
            *(float4*)(a + 4)  = *(const float4*)&As[kk][ty * 8 + 4];
            *(float4*)(bq)     = *(const float4*)&Ws[kk][tx * 8];
            *(float4*)(bq + 4) = *(const float4*)&Ws[kk][tx * 8 + 4];
#pragma unroll
            for (int i = 0; i < 8; i++)
#pragma unroll
                for (int j = 0; j < 8; j++)
                    acc[i][j] += a[i] * bq[j];
        }
        __syncthreads();
    }

#pragma unroll
    for (int i = 0; i < 8; i++) {
        const long row = m0 + ty * 8 + i;
#pragma unroll
        for (int j = 0; j < 8; j++) {
            const int col = n0 + tx * 8 + j;
            if (col < N) {
                float v = acc[i][j];
                if (bias)  v += bias[col];
                if (accum) v += C[row * ldc + col];
                C[row * ldc + col] = v;
            }
        }
    }
}

// ---------------- stage 3: input attention + top-k mask + rnn_in ---------------
__global__ void __launch_bounds__(128) attn_kernel(const float* __restrict__ kb,
                                                   const float* __restrict__ vb)
{
    const int b = blockIdx.x;
    const int t = threadIdx.x;
    __shared__ float sq[NRIM * 128], skx[128], skb[128];
    __shared__ float s2[12], sm[NRIM], sp0[NRIM], sp1[NRIM];

    for (int i = t; i < NRIM * 128; i += 128) sq[i] = g_q[b * NRIM * 128 + i];
    if (t < 128) { skx[t] = g_kx[b * 128 + t]; skb[t] = kb[t]; }
    __syncthreads();

    // scores2[n][m] = dot128(q[b,n], {kx|key_b}) / (NIH*sqrt(IKS)) = /16
    const int w = t >> 5, lane = t & 31;
    for (int d = w; d < 12; d += 4) {
        const int n = d >> 1, m = d & 1;
        const float* kv = m ? skb : skx;
        float s = 0.f;
        for (int k = lane; k < 128; k += 32) s += sq[n * 128 + k] * kv[k];
#pragma unroll
        for (int o = 16; o; o >>= 1) s += __shfl_xor_sync(0xffffffffu, s, o);
        if (!lane) s2[d] = s * (1.0f / 16.0f);
    }
    __syncthreads();

    if (t < NRIM) {
        const int n = t;
        const float sn = s2[n * 2];
        int rank = 0;
        for (int m2 = 0; m2 < NRIM; m2++) {
            const float sv = s2[m2 * 2];
            if (sv > sn || (sv == sn && m2 < n)) rank++;
        }
        const float mk = (rank < TOPK) ? 1.0f : 0.0f;
        sm[n] = mk;
        g_mask[b * NRIM + n] = mk;
        const float a0 = s2[n * 2], a1 = s2[n * 2 + 1];
        const float mx = fmaxf(a0, a1);
        const float e0 = expf(a0 - mx), e1 = expf(a1 - mx);
        const float inv = 1.0f / (e0 + e1);
        sp0[n] = e0 * inv;
        sp1[n] = e1 * inv;
    }
    __syncthreads();

    for (int v = t; v < IVS; v += 128) {
        const float v20 = 0.5f * (g_vx[b * 800 + v] + g_vx[b * 800 + 400 + v]);
        const float v21 = 0.5f * (vb[v] + vb[400 + v]);
#pragma unroll
        for (int n = 0; n < NRIM; n++)
            g_rnn[(b * NRIM + n) * IVS + v] = sm[n] * (sp0[n] * v20 + sp1[n] * v21);
    }
}

// ---------------- stage 5: LSTM pointwise; writes c_upd to out[2*BF..] ----------
__global__ void lstm_kernel(const float* __restrict__ cs, float* __restrict__ out)
{
    const int i = blockIdx.x * blockDim.x + threadIdx.x;
    if (i >= BF) return;
    const int bn = i >> 8;   // b*NRIM + n
    const int u  = i & 255;
    const float* p = g_pre + (long)bn * 1024;
    const float nc = tanhf(p[u]);
    const float ig = 1.f / (1.f + expf(-p[256 + u]));
    const float fg = 1.f / (1.f + expf(-p[512 + u]));
    const float og = 1.f / (1.f + expf(-p[768 + u]));
    const float c  = cs[i] * fg + ig * nc;
    const float h  = og * tanhf(c);
    g_hnew[i] = h;
    const float m = g_mask[bn];
    out[2L * BF + i] = (m != 0.f) ? c : cs[i];
}

// ---------------- stage 7: communication attention ------------------------------
__global__ void __launch_bounds__(128) cattn_kernel()
{
    const int b = blockIdx.x;
    const int t = threadIdx.x;
    __shared__ float sk[NRIM * 128], sq[NRIM * 128], sv[NRIM * 400];
    __shared__ float sm[NRIM], sc[144], sp[144];

    for (int i = t; i < NRIM * 128; i += 128) {
        sk[i] = g_ck[b * NRIM * 128 + i];
        sq[i] = g_cq[b * NRIM * 128 + i];
    }
    for (int i = t; i < NRIM * 400; i += 128) sv[i] = g_cv[b * NRIM * 400 + i];
    if (t < NRIM) sm[t] = g_mask[b * NRIM + t];
    __syncthreads();

    // c_scores[h][n][m]
    for (int d = t; d < 144; d += 128) {
        const int h = d / 36, r = d % 36, n = r / 6, m = r % 6;
        float s = 0.f;
#pragma unroll
        for (int k = 0; k < CKS; k++)
            s += sq[n * 128 + h * CKS + k] * sk[m * 128 + h * CKS + k];
        sc[d] = s * 0.17677669529663687f;   // 1/sqrt(32)
    }
    __syncthreads();

    if (t < 24) {
        const int h = t / 6, n = t % 6;
        float mx = -1e30f;
        for (int m = 0; m < 6; m++) mx = fmaxf(mx, sc[h * 36 + n * 6 + m]);
        float e[6], sum = 0.f;
        for (int m = 0; m < 6; m++) { e[m] = expf(sc[h * 36 + n * 6 + m] - mx); sum += e[m]; }
        const float inv = sm[n] / sum;     // row mask folded into softmax scale
        for (int m = 0; m < 6; m++) sp[h * 36 + n * 6 + m] = e[m] * inv;
    }
    __syncthreads();

    // ctx[b,n, h*100+v] = sum_m probs[h,n,m] * cv[b,m,h*100+v]
    for (int idx = t; idx < NRIM * 400; idx += 128) {
        const int n = idx / 400, r = idx % 400, h = r / 100;
        float a = 0.f;
#pragma unroll
        for (int m = 0; m < 6; m++) a += sp[h * 36 + n * 6 + m] * sv[m * 400 + r];
        g_ctx[b * NRIM * 400 + idx] = a;
    }
}

// ---------------- stage 9: final h update, write out[0..BF) and [BF..2BF) ------
__global__ void final_kernel(const float* __restrict__ hs, float* __restrict__ out)
{
    const int i = blockIdx.x * blockDim.x + threadIdx.x;
    if (i >= BF) return;
    const int bn = i >> 8;
    const float m = g_mask[bn];
    const float h = (m != 0.f) ? (g_hcm[i] + g_hnew[i]) : hs[i];
    out[i]      = h;
    out[BF + i] = h;
}

// -------------------------------------------------------------------------------
extern "C" void kernel_launch(void* const* d_in, const int* in_sizes, int n_in,
                              void* d_out, int out_size)
{
    const float* x     = (const float*)d_in[0];
    const float* hs    = (const float*)d_in[1];
    const float* cs    = (const float*)d_in[2];
    const float* keyW  = (const float*)d_in[3];
    const float* keyb  = (const float*)d_in[4];
    const float* valW  = (const float*)d_in[5];
    const float* valb  = (const float*)d_in[6];
    const float* qW    = (const float*)d_in[7];
    const float* i2h   = (const float*)d_in[8];
    const float* h2h   = (const float*)d_in[9];
    const float* WkC   = (const float*)d_in[10];
    const float* WvC   = (const float*)d_in[11];
    const float* WqC   = (const float*)d_in[12];
    const float* WoC   = (const float*)d_in[13];
    float* out = (float*)d_out;

    float *kx, *vx, *q, *rnn, *pre, *ck, *cv, *cq, *ctx, *hcm, *hnew;
    cudaGetSymbolAddress((void**)&kx,  g_kx);
    cudaGetSymbolAddress((void**)&vx,  g_vx);
    cudaGetSymbolAddress((void**)&q,   g_q);
    cudaGetSymbolAddress((void**)&rnn, g_rnn);
    cudaGetSymbolAddress((void**)&pre, g_pre);
    cudaGetSymbolAddress((void**)&ck,  g_ck);
    cudaGetSymbolAddress((void**)&cv,  g_cv);
    cudaGetSymbolAddress((void**)&cq,  g_cq);
    cudaGetSymbolAddress((void**)&ctx, g_ctx);
    cudaGetSymbolAddress((void**)&hcm, g_hcm);
    cudaGetSymbolAddress((void**)&hnew, g_hnew);

    const dim3 blk(256);
    auto grid = [](int N, int batch) { return dim3((N + 127) / 128, BSZ / 128, batch); };

    // 1) kx = x @ key_W + key_b            (8192x512)x(512x128)
    gemm128<<<grid(128, 1), blk>>>(x, keyW, keyb, kx, 128, 512, 512, 128, 128, 0, 0, 0, 0);
    // 2) vx = x @ value_W + value_b        (8192x512)x(512x800)
    gemm128<<<grid(800, 1), blk>>>(x, valW, valb, vx, 800, 512, 512, 800, 800, 0, 0, 0, 0);
    // 3) q[:,n,:] = hs[:,n,:] @ query_W[n] (8192x256)x(256x128), batched n
    gemm128<<<grid(128, NRIM), blk>>>(hs, qW, nullptr, q, 128, 256, NRIM * UNITS, 128,
                                      NRIM * 128, UNITS, 256L * 128, 128, 0);
    // 4) input attention + top-k + rnn_in
    attn_kernel<<<BSZ, 128>>>(keyb, valb);
    // 5) preact = rnn_in @ i2h[n]
    gemm128<<<grid(1024, NRIM), blk>>>(rnn, i2h, nullptr, pre, 1024, IVS, NRIM * IVS, 1024,
                                       NRIM * 1024, IVS, (long)IVS * 1024, 1024, 0);
    // 6) preact += hs @ h2h[n]
    gemm128<<<grid(1024, NRIM), blk>>>(hs, h2h, nullptr, pre, 1024, 256, NRIM * UNITS, 1024,
                                       NRIM * 1024, UNITS, 256L * 1024, 1024, 1);
    // 7) LSTM pointwise (+ writes c_upd)
    lstm_kernel<<<(BF + 255) / 256, 256>>>(cs, out);
    // 8) ck/cv/cq = h_new @ W*_comm[n]
    gemm128<<<grid(128, NRIM), blk>>>(hnew, WkC, nullptr, ck, 128, 256, NRIM * UNITS, 128,
                                      NRIM * 128, UNITS, 256L * 128, 128, 0);
    gemm128<<<grid(400, NRIM), blk>>>(hnew, WvC, nullptr, cv, 400, 256, NRIM * UNITS, 400,
                                      NRIM * 400, UNITS, 256L * 400, 400, 0);
    gemm128<<<grid(128, NRIM), blk>>>(hnew, WqC, nullptr, cq, 128, 256, NRIM * UNITS, 128,
                                      NRIM * 128, UNITS, 256L * 128, 128, 0);
    // 9) communication attention -> ctx
    cattn_kernel<<<BSZ, 128>>>();
    // 10) hcm = ctx @ Wout_comm[n]
    gemm128<<<grid(256, NRIM), blk>>>(ctx, WoC, nullptr, hcm, 256, 400, NRIM * 400, 256,
                                      NRIM * UNITS, 400, 400L * 256, UNITS, 0);
    // 11) final h update -> out[0..BF), out[BF..2BF)
    final_kernel<<<(BF + 255) / 256, 256>>>(hs, out);
}

// round 3
// speedup vs baseline: 1.8311x; 1.8311x over previous
#include <cuda_runtime.h>
#include <math.h>
#include <stdint.h>

#define BSZ   8192
#define DD    512
#define UNITS 256
#define NRIM  6
#define TOPK  4
#define NIH   2
#define IKS   64
#define IVS   400
#define NCH   4
#define CKS   32
#define CVS   100

#define BF (BSZ*NRIM*UNITS)   // 8192*1536

// ---------------- scratch (device globals; no allocations allowed) ------------
__device__ float g_kx  [BSZ*128];
__device__ float g_vx  [BSZ*800];
__device__ float g_q   [BSZ*NRIM*128];
__device__ float g_mask[BSZ*NRIM];
__device__ float g_rnn [BSZ*NRIM*IVS];
__device__ float g_pre [BSZ*NRIM*1024];
__device__ float g_hnew[BSZ*NRIM*UNITS];
__device__ float g_ck  [BSZ*NRIM*128];
__device__ float g_cv  [BSZ*NRIM*400];
__device__ float g_cq  [BSZ*NRIM*128];
__device__ float g_ctx [BSZ*NRIM*400];
__device__ float g_hcm [BSZ*NRIM*UNITS];

// =================== fp32 GEMM (kept for the top-k-sensitive path) ============
__global__ void __launch_bounds__(256) gemm128(
    const float* __restrict__ A, const float* __restrict__ W,
    const float* __restrict__ bias, float* __restrict__ C,
    int N, int Kd, int lda, int ldw, int ldc,
    long sA, long sW, long sC, int accum)
{
    A += (long)blockIdx.z * sA;
    W += (long)blockIdx.z * sW;
    C += (long)blockIdx.z * sC;

    __shared__ float As[8][128];
    __shared__ float Ws[8][128];

    const int tid = threadIdx.x;
    const int m0  = blockIdx.y * 128;
    const int n0  = blockIdx.x * 128;

    const int aRow = tid >> 1;
    const int aK   = (tid & 1) * 4;
    const int wK   = tid >> 5;
    const int wC   = (tid & 31) * 4;
    const int ty   = tid >> 4;
    const int tx   = tid & 15;

    float acc[8][8];
#pragma unroll
    for (int i = 0; i < 8; i++)
#pragma unroll
        for (int j = 0; j < 8; j++) acc[i][j] = 0.f;

    const float* Aptr = A + (long)(m0 + aRow) * lda + aK;

    for (int k0 = 0; k0 < Kd; k0 += 8) {
        float4 av = *(const float4*)(Aptr + k0);
        As[aK + 0][aRow] = av.x;
        As[aK + 1][aRow] = av.y;
        As[aK + 2][aRow] = av.z;
        As[aK + 3][aRow] = av.w;
        {
            const int col = n0 + wC;
            const float* wp = W + (long)(k0 + wK) * ldw;
            if (col + 3 < N) {
                *(float4*)&Ws[wK][wC] = *(const float4*)(wp + col);
            } else {
#pragma unroll
                for (int j = 0; j < 4; j++)
                    Ws[wK][wC + j] = (col + j < N) ? wp[col + j] : 0.f;
            }
        }
        __syncthreads();

#pragma unroll
        for (int kk = 0; kk < 8; kk++) {
            float a[8], bq[8];
            *(float4*)(a)      = *(const float4*)&As[kk][ty * 8];
            *(float4*)(a + 4)  = *(const float4*)&As[kk][ty * 8 + 4];
            *(float4*)(bq)     = *(const float4*)&Ws[kk][tx * 8];
            *(float4*)(bq + 4) = *(const float4*)&Ws[kk][tx * 8 + 4];
#pragma unroll
            for (int i = 0; i < 8; i++)
#pragma unroll
                for (int j = 0; j < 8; j++)
                    acc[i][j] += a[i] * bq[j];
        }
        __syncthreads();
    }

#pragma unroll
    for (int i = 0; i < 8; i++) {
        const long row = m0 + ty * 8 + i;
#pragma unroll
        for (int j = 0; j < 8; j++) {
            const int col = n0 + tx * 8 + j;
            if (col < N) {
                float v = acc[i][j];
                if (bias)  v += bias[col];
                if (accum) v += C[row * ldc + col];
                C[row * ldc + col] = v;
            }
        }
    }
}

// =================== tf32 tensor-core GEMM ====================================
// C[M x N] = A[M x K] * W[K x N], tile 128x128x16, 8 warps (2 M x 4 N),
// warp tile 64x32 via mma.sync.m16n8k8.row.col tf32.
__device__ __forceinline__ uint32_t f2tf(float x) {
    uint32_t r;
    asm("cvt.rna.tf32.f32 %0, %1;" : "=r"(r) : "f"(x));
    return r;
}
__device__ __forceinline__ void mma_tf32(float* d, const uint32_t* a,
                                         const uint32_t* b, const float* c) {
    asm volatile(
        "mma.sync.aligned.m16n8k8.row.col.f32.tf32.tf32.f32 "
        "{%0,%1,%2,%3}, {%4,%5,%6,%7}, {%8,%9}, {%10,%11,%12,%13};\n"
        : "=f"(d[0]), "=f"(d[1]), "=f"(d[2]), "=f"(d[3])
        : "r"(a[0]), "r"(a[1]), "r"(a[2]), "r"(a[3]),
          "r"(b[0]), "r"(b[1]),
          "f"(c[0]), "f"(c[1]), "f"(c[2]), "f"(c[3]));
}

__global__ void __launch_bounds__(256) gemm_tf32(
    const float* __restrict__ A, const float* __restrict__ W,
    const float* __restrict__ bias, float* __restrict__ C,
    int N, int Kd, int lda, int ldw, int ldc,
    long sA, long sW, long sC, int accum)
{
    A += (long)blockIdx.z * sA;
    W += (long)blockIdx.z * sW;
    C += (long)blockIdx.z * sC;

    __shared__ uint32_t As[128][20];   // [m][k], pad 20 -> conflict-free frag reads
    __shared__ uint32_t Ws[16][136];   // [k][n], pad 136 -> conflict-free frag reads

    const int tid    = threadIdx.x;
    const int wid    = tid >> 5;
    const int lane   = tid & 31;
    const int warp_m = (wid & 1) * 64;
    const int warp_n = (wid >> 1) * 32;
    const int g      = lane >> 2;      // 0..7
    const int qd     = lane & 3;       // 0..3
    const int m0     = blockIdx.y * 128;
    const int n0     = blockIdx.x * 128;

    const int aRow = tid >> 1;         // 0..127
    const int aK   = (tid & 1) * 4;    // 0 or 4 (plus +8)
    const int wK   = wid;              // 0..7 (plus +8)
    const int wC   = lane * 4;         // 0..124

    float acc[4][4][4];
#pragma unroll
    for (int i = 0; i < 4; i++)
#pragma unroll
        for (int j = 0; j < 4; j++)
#pragma unroll
            for (int r = 0; r < 4; r++) acc[i][j][r] = 0.f;

    const float* Aptr = A + (long)(m0 + aRow) * lda;

    for (int k0 = 0; k0 < Kd; k0 += 16) {
        // ---- A tile: [m][k], tf32-rounded ----
        float4 av0 = *(const float4*)(Aptr + k0 + aK);
        float4 av1 = *(const float4*)(Aptr + k0 + aK + 8);
        {
            uint4 u0 = { f2tf(av0.x), f2tf(av0.y), f2tf(av0.z), f2tf(av0.w) };
            uint4 u1 = { f2tf(av1.x), f2tf(av1.y), f2tf(av1.z), f2tf(av1.w) };
            *(uint4*)&As[aRow][aK]     = u0;
            *(uint4*)&As[aRow][aK + 8] = u1;
        }
        // ---- W tile: [k][n], two rows per thread, N guard ----
#pragma unroll
        for (int h = 0; h < 2; h++) {
            const int kk  = wK + h * 8;
            const int col = n0 + wC;
            const float* wp = W + (long)(k0 + kk) * ldw;
            float4 wv;
            if (col + 3 < N) {
                wv = *(const float4*)(wp + col);
            } else {
                wv.x = (col + 0 < N) ? wp[col + 0] : 0.f;
                wv.y = (col + 1 < N) ? wp[col + 1] : 0.f;
                wv.z = (col + 2 < N) ? wp[col + 2] : 0.f;
                wv.w = (col + 3 < N) ? wp[col + 3] : 0.f;
            }
            uint4 u = { f2tf(wv.x), f2tf(wv.y), f2tf(wv.z), f2tf(wv.w) };
            *(uint4*)&Ws[kk][wC] = u;
        }
        __syncthreads();

#pragma unroll
        for (int ks = 0; ks < 16; ks += 8) {
            uint32_t af[4][4], bf[4][2];
#pragma unroll
            for (int i = 0; i < 4; i++) {
                const int mb = warp_m + i * 16 + g;
                af[i][0] = As[mb    ][ks + qd];
                af[i][1] = As[mb + 8][ks + qd];
                af[i][2] = As[mb    ][ks + qd + 4];
                af[i][3] = As[mb + 8][ks + qd + 4];
            }
#pragma unroll
            for (int j = 0; j < 4; j++) {
                const int nb = warp_n + j * 8 + g;
                bf[j][0] = Ws[ks + qd    ][nb];
                bf[j][1] = Ws[ks + qd + 4][nb];
            }
#pragma unroll
            for (int i = 0; i < 4; i++)
#pragma unroll
                for (int j = 0; j < 4; j++)
                    mma_tf32(acc[i][j], af[i], bf[j], acc[i][j]);
        }
        __syncthreads();
    }

    // ---- epilogue ----
#pragma unroll
    for (int i = 0; i < 4; i++) {
        const long mA = m0 + warp_m + i * 16 + g;
        const long mB = mA + 8;
#pragma unroll
        for (int j = 0; j < 4; j++) {
            const int n = n0 + warp_n + j * 8 + qd * 2;
#pragma unroll
            for (int e = 0; e < 2; e++) {
                const int col = n + e;
                if (col < N) {
                    float vA = acc[i][j][e];
                    float vB = acc[i][j][2 + e];
                    if (bias)  { vA += bias[col]; vB += bias[col]; }
                    if (accum) { vA += C[mA * ldc + col]; vB += C[mB * ldc + col]; }
                    C[mA * ldc + col] = vA;
                    C[mB * ldc + col] = vB;
                }
            }
        }
    }
}

// ---------------- input attention + top-k mask + rnn_in ------------------------
__global__ void __launch_bounds__(128) attn_kernel(const float* __restrict__ kb,
                                                   const float* __restrict__ vb)
{
    const int b = blockIdx.x;
    const int t = threadIdx.x;
    __shared__ float sq[NRIM * 128], skx[128], skb[128];
    __shared__ float s2[12], sm[NRIM], sp0[NRIM], sp1[NRIM];

    for (int i = t; i < NRIM * 128; i += 128) sq[i] = g_q[b * NRIM * 128 + i];
    if (t < 128) { skx[t] = g_kx[b * 128 + t]; skb[t] = kb[t]; }
    __syncthreads();

    const int w = t >> 5, lane = t & 31;
    for (int d = w; d < 12; d += 4) {
        const int n = d >> 1, m = d & 1;
        const float* kv = m ? skb : skx;
        float s = 0.f;
        for (int k = lane; k < 128; k += 32) s += sq[n * 128 + k] * kv[k];
#pragma unroll
        for (int o = 16; o; o >>= 1) s += __shfl_xor_sync(0xffffffffu, s, o);
        if (!lane) s2[d] = s * (1.0f / 16.0f);
    }
    __syncthreads();

    if (t < NRIM) {
        const int n = t;
        const float sn = s2[n * 2];
        int rank = 0;
        for (int m2 = 0; m2 < NRIM; m2++) {
            const float sv = s2[m2 * 2];
            if (sv > sn || (sv == sn && m2 < n)) rank++;
        }
        const float mk = (rank < TOPK) ? 1.0f : 0.0f;
        sm[n] = mk;
        g_mask[b * NRIM + n] = mk;
        const float a0 = s2[n * 2], a1 = s2[n * 2 + 1];
        const float mx = fmaxf(a0, a1);
        const float e0 = expf(a0 - mx), e1 = expf(a1 - mx);
        const float inv = 1.0f / (e0 + e1);
        sp0[n] = e0 * inv;
        sp1[n] = e1 * inv;
    }
    __syncthreads();

    for (int v = t; v < IVS; v += 128) {
        const float v20 = 0.5f * (g_vx[b * 800 + v] + g_vx[b * 800 + 400 + v]);
        const float v21 = 0.5f * (vb[v] + vb[400 + v]);
#pragma unroll
        for (int n = 0; n < NRIM; n++)
            g_rnn[(b * NRIM + n) * IVS + v] = sm[n] * (sp0[n] * v20 + sp1[n] * v21);
    }
}

// ---------------- LSTM pointwise; writes c_upd to out[2*BF..] -------------------
__global__ void lstm_kernel(const float* __restrict__ cs, float* __restrict__ out)
{
    const int i = blockIdx.x * blockDim.x + threadIdx.x;
    if (i >= BF) return;
    const int bn = i >> 8;
    const int u  = i & 255;
    const float* p = g_pre + (long)bn * 1024;
    const float nc = tanhf(p[u]);
    const float ig = 1.f / (1.f + expf(-p[256 + u]));
    const float fg = 1.f / (1.f + expf(-p[512 + u]));
    const float og = 1.f / (1.f + expf(-p[768 + u]));
    const float c  = cs[i] * fg + ig * nc;
    const float h  = og * tanhf(c);
    g_hnew[i] = h;
    const float m = g_mask[bn];
    out[2L * BF + i] = (m != 0.f) ? c : cs[i];
}

// ---------------- communication attention --------------------------------------
__global__ void __launch_bounds__(128) cattn_kernel()
{
    const int b = blockIdx.x;
    const int t = threadIdx.x;
    __shared__ float sk[NRIM * 128], sq[NRIM * 128], sv[NRIM * 400];
    __shared__ float sm[NRIM], sc[144], sp[144];

    for (int i = t; i < NRIM * 128; i += 128) {
        sk[i] = g_ck[b * NRIM * 128 + i];
        sq[i] = g_cq[b * NRIM * 128 + i];
    }
    for (int i = t; i < NRIM * 400; i += 128) sv[i] = g_cv[b * NRIM * 400 + i];
    if (t < NRIM) sm[t] = g_mask[b * NRIM + t];
    __syncthreads();

    for (int d = t; d < 144; d += 128) {
        const int h = d / 36, r = d % 36, n = r / 6, m = r % 6;
        float s = 0.f;
#pragma unroll
        for (int k = 0; k < CKS; k++)
            s += sq[n * 128 + h * CKS + k] * sk[m * 128 + h * CKS + k];
        sc[d] = s * 0.17677669529663687f;
    }
    __syncthreads();

    if (t < 24) {
        const int h = t / 6, n = t % 6;
        float mx = -1e30f;
        for (int m = 0; m < 6; m++) mx = fmaxf(mx, sc[h * 36 + n * 6 + m]);
        float e[6], sum = 0.f;
        for (int m = 0; m < 6; m++) { e[m] = expf(sc[h * 36 + n * 6 + m] - mx); sum += e[m]; }
        const float inv = sm[n] / sum;
        for (int m = 0; m < 6; m++) sp[h * 36 + n * 6 + m] = e[m] * inv;
    }
    __syncthreads();

    for (int idx = t; idx < NRIM * 400; idx += 128) {
        const int n = idx / 400, r = idx % 400, h = r / 100;
        float a = 0.f;
#pragma unroll
        for (int m = 0; m < 6; m++) a += sp[h * 36 + n * 6 + m] * sv[m * 400 + r];
        g_ctx[b * NRIM * 400 + idx] = a;
    }
}

// ---------------- final h update ------------------------------------------------
__global__ void final_kernel(const float* __restrict__ hs, float* __restrict__ out)
{
    const int i = blockIdx.x * blockDim.x + threadIdx.x;
    if (i >= BF) return;
    const int bn = i >> 8;
    const float m = g_mask[bn];
    const float h = (m != 0.f) ? (g_hcm[i] + g_hnew[i]) : hs[i];
    out[i]      = h;
    out[BF + i] = h;
}

// -------------------------------------------------------------------------------
extern "C" void kernel_launch(void* const* d_in, const int* in_sizes, int n_in,
                              void* d_out, int out_size)
{
    const float* x     = (const float*)d_in[0];
    const float* hs    = (const float*)d_in[1];
    const float* cs    = (const float*)d_in[2];
    const float* keyW  = (const float*)d_in[3];
    const float* keyb  = (const float*)d_in[4];
    const float* valW  = (const float*)d_in[5];
    const float* valb  = (const float*)d_in[6];
    const float* qW    = (const float*)d_in[7];
    const float* i2h   = (const float*)d_in[8];
    const float* h2h   = (const float*)d_in[9];
    const float* WkC   = (const float*)d_in[10];
    const float* WvC   = (const float*)d_in[11];
    const float* WqC   = (const float*)d_in[12];
    const float* WoC   = (const float*)d_in[13];
    float* out = (float*)d_out;

    float *kx, *vx, *q, *rnn, *pre, *ck, *cv, *cq, *ctx, *hcm, *hnew;
    cudaGetSymbolAddress((void**)&kx,  g_kx);
    cudaGetSymbolAddress((void**)&vx,  g_vx);
    cudaGetSymbolAddress((void**)&q,   g_q);
    cudaGetSymbolAddress((void**)&rnn, g_rnn);
    cudaGetSymbolAddress((void**)&pre, g_pre);
    cudaGetSymbolAddress((void**)&ck,  g_ck);
    cudaGetSymbolAddress((void**)&cv,  g_cv);
    cudaGetSymbolAddress((void**)&cq,  g_cq);
    cudaGetSymbolAddress((void**)&ctx, g_ctx);
    cudaGetSymbolAddress((void**)&hcm, g_hcm);
    cudaGetSymbolAddress((void**)&hnew, g_hnew);

    const dim3 blk(256);
    auto grid = [](int N, int batch) { return dim3((N + 127) / 128, BSZ / 128, batch); };

    // 1) kx = x @ key_W + key_b  (fp32: feeds top-k signal)
    gemm128<<<grid(128, 1), blk>>>(x, keyW, keyb, kx, 128, 512, 512, 128, 128, 0, 0, 0, 0);
    // 2) vx = x @ value_W + value_b  (tf32)
    gemm_tf32<<<grid(800, 1), blk>>>(x, valW, valb, vx, 800, 512, 512, 800, 800, 0, 0, 0, 0);
    // 3) q = hs @ query_W[n]  (fp32: feeds top-k signal)
    gemm128<<<grid(128, NRIM), blk>>>(hs, qW, nullptr, q, 128, 256, NRIM * UNITS, 128,
                                      NRIM * 128, UNITS, 256L * 128, 128, 0);
    // 4) input attention + top-k + rnn_in
    attn_kernel<<<BSZ, 128>>>(keyb, valb);
    // 5) preact = rnn_in @ i2h[n]  (tf32)
    gemm_tf32<<<grid(1024, NRIM), blk>>>(rnn, i2h, nullptr, pre, 1024, IVS, NRIM * IVS, 1024,
                                         NRIM * 1024, IVS, (long)IVS * 1024, 1024, 0);
    // 6) preact += hs @ h2h[n]  (tf32)
    gemm_tf32<<<grid(1024, NRIM), blk>>>(hs, h2h, nullptr, pre, 1024, 256, NRIM * UNITS, 1024,
                                         NRIM * 1024, UNITS, 256L * 1024, 1024, 1);
    // 7) LSTM pointwise
    lstm_kernel<<<(BF + 255) / 256, 256>>>(cs, out);
    // 8) ck/cv/cq = h_new @ W*_comm[n]  (tf32)
    gemm_tf32<<<grid(128, NRIM), blk>>>(hnew, WkC, nullptr, ck, 128, 256, NRIM * UNITS, 128,
                                        NRIM * 128, UNITS, 256L * 128, 128, 0);
    gemm_tf32<<<grid(400, NRIM), blk>>>(hnew, WvC, nullptr, cv, 400, 256, NRIM * UNITS, 400,
                                        NRIM * 400, UNITS, 256L * 400, 400, 0);
    gemm_tf32<<<grid(128, NRIM), blk>>>(hnew, WqC, nullptr, cq, 128, 256, NRIM * UNITS, 128,
                                        NRIM * 128, UNITS, 256L * 128, 128, 0);
    // 9) communication attention -> ctx
    cattn_kernel<<<BSZ, 128>>>();
    // 10) hcm = ctx @ Wout_comm[n]  (tf32)
    gemm_tf32<<<grid(256, NRIM), blk>>>(ctx, WoC, nullptr, hcm, 256, 400, NRIM * 400, 256,
                                        NRIM * UNITS, 400, 400L * 256, UNITS, 0);
    // 11) final h update
    final_kernel<<<(BF + 255) / 256, 256>>>(hs, out);
}

// round 4
// speedup vs baseline: 2.2121x; 1.2081x over previous
#include <cuda_runtime.h>
#include <math.h>
#include <stdint.h>

#define BSZ   8192
#define DD    512
#define UNITS 256
#define NRIM  6
#define TOPK  4
#define NIH   2
#define IKS   64
#define IVS   400
#define NCH   4
#define CKS   32
#define CVS   100

#define BF (BSZ*NRIM*UNITS)

// ---------------- scratch ------------------------------------------------------
__device__ float g_kx  [BSZ*128];
__device__ float g_vx  [BSZ*800];
__device__ float g_q   [BSZ*NRIM*128];
__device__ float g_mask[BSZ*NRIM];
__device__ float g_rnn [BSZ*NRIM*IVS];
__device__ float g_pre [BSZ*NRIM*1024];
__device__ float g_hnew[BSZ*NRIM*UNITS];
__device__ float g_ck  [BSZ*NRIM*128];
__device__ float g_cv  [BSZ*NRIM*400];
__device__ float g_cq  [BSZ*NRIM*128];
__device__ float g_ctx [BSZ*NRIM*400];
__device__ float g_hcm [BSZ*NRIM*UNITS];

// =================== fp32 GEMM (top-k-sensitive path only) ====================
__global__ void __launch_bounds__(256) gemm128(
    const float* __restrict__ A, const float* __restrict__ W,
    const float* __restrict__ bias, float* __restrict__ C,
    int N, int Kd, int lda, int ldw, int ldc,
    long sA, long sW, long sC, int accum)
{
    A += (long)blockIdx.z * sA;
    W += (long)blockIdx.z * sW;
    C += (long)blockIdx.z * sC;

    __shared__ float As[8][128];
    __shared__ float Ws[8][128];

    const int tid = threadIdx.x;
    const int m0  = blockIdx.y * 128;
    const int n0  = blockIdx.x * 128;

    const int aRow = tid >> 1;
    const int aK   = (tid & 1) * 4;
    const int wK   = tid >> 5;
    const int wC   = (tid & 31) * 4;
    const int ty   = tid >> 4;
    const int tx   = tid & 15;

    float acc[8][8];
#pragma unroll
    for (int i = 0; i < 8; i++)
#pragma unroll
        for (int j = 0; j < 8; j++) acc[i][j] = 0.f;

    const float* Aptr = A + (long)(m0 + aRow) * lda + aK;

    for (int k0 = 0; k0 < Kd; k0 += 8) {
        float4 av = *(const float4*)(Aptr + k0);
        As[aK + 0][aRow] = av.x;
        As[aK + 1][aRow] = av.y;
        As[aK + 2][aRow] = av.z;
        As[aK + 3][aRow] = av.w;
        {
            const int col = n0 + wC;
            const float* wp = W + (long)(k0 + wK) * ldw;
            if (col + 3 < N) {
                *(float4*)&Ws[wK][wC] = *(const float4*)(wp + col);
            } else {
#pragma unroll
                for (int j = 0; j < 4; j++)
                    Ws[wK][wC + j] = (col + j < N) ? wp[col + j] : 0.f;
            }
        }
        __syncthreads();

#pragma unroll
        for (int kk = 0; kk < 8; kk++) {
            float a[8], bq[8];
            *(float4*)(a)      = *(const float4*)&As[kk][ty * 8];
            *(float4*)(a + 4)  = *(const float4*)&As[kk][ty * 8 + 4];
            *(float4*)(bq)     = *(const float4*)&Ws[kk][tx * 8];
            *(float4*)(bq + 4) = *(const float4*)&Ws[kk][tx * 8 + 4];
#pragma unroll
            for (int i = 0; i < 8; i++)
#pragma unroll
                for (int j = 0; j < 8; j++)
                    acc[i][j] += a[i] * bq[j];
        }
        __syncthreads();
    }

#pragma unroll
    for (int i = 0; i < 8; i++) {
        const long row = m0 + ty * 8 + i;
#pragma unroll
        for (int j = 0; j < 8; j++) {
            const int col = n0 + tx * 8 + j;
            if (col < N) {
                float v = acc[i][j];
                if (bias)  v += bias[col];
                if (accum) v += C[row * ldc + col];
                C[row * ldc + col] = v;
            }
        }
    }
}

// =================== tf32 tensor-core GEMM v2 =================================
// C = A1[M x K1] * W1 + A2[M x K2] * W2 (+bias).  Tile 128x128, BK=32,
// register-staged double buffering, 8 warps (2Mx4N), warp tile 64x32.
__device__ __forceinline__ uint32_t f2tf(float x) {
    uint32_t r;
    asm("cvt.rna.tf32.f32 %0, %1;" : "=r"(r) : "f"(x));
    return r;
}
__device__ __forceinline__ void mma_tf32(float* d, const uint32_t* a,
                                         const uint32_t* b, const float* c) {
    asm volatile(
        "mma.sync.aligned.m16n8k8.row.col.f32.tf32.tf32.f32 "
        "{%0,%1,%2,%3}, {%4,%5,%6,%7}, {%8,%9}, {%10,%11,%12,%13};\n"
        : "=f"(d[0]), "=f"(d[1]), "=f"(d[2]), "=f"(d[3])
        : "r"(a[0]), "r"(a[1]), "r"(a[2]), "r"(a[3]),
          "r"(b[0]), "r"(b[1]),
          "f"(c[0]), "f"(c[1]), "f"(c[2]), "f"(c[3]));
}

__global__ void __launch_bounds__(256) gemm_tf32_v2(
    const float* __restrict__ A1, const float* __restrict__ W1, int K1, int lda1, int ldw1,
    const float* __restrict__ A2, const float* __restrict__ W2, int K2, int lda2, int ldw2,
    const float* __restrict__ bias, float* __restrict__ C, int N, int ldc,
    long sA1, long sW1, long sA2, long sW2, long sC)
{
    A1 += (long)blockIdx.z * sA1;
    W1 += (long)blockIdx.z * sW1;
    A2 += (long)blockIdx.z * sA2;
    W2 += (long)blockIdx.z * sW2;
    C  += (long)blockIdx.z * sC;

    const int K1p  = (K1 + 31) & ~31;
    const int Ktot = K1p + ((K2 + 31) & ~31);

    __shared__ uint32_t As[128][36];   // [m][k], pad 36: frag bank == lane (conflict-free)
    __shared__ uint32_t Ws[32][132];   // [k][n], pad 132: frag bank == lane

    const int tid    = threadIdx.x;
    const int wid    = tid >> 5;
    const int lane   = tid & 31;
    const int warp_m = (wid & 1) * 64;
    const int warp_n = (wid >> 1) * 32;
    const int g      = lane >> 2;
    const int qd     = lane & 3;
    const int m0     = blockIdx.y * 128;
    const int n0     = blockIdx.x * 128;

    const int aRow = tid >> 1;          // 0..127
    const int aKc  = (tid & 1) * 16;    // 0 or 16
    const int wRow = wid;               // 0..7 (+8h)
    const int wCol = lane * 4;          // 0..124

    float4 a_st[4], w_st[4];

    // --- staged loads (guarded, dual-segment, zero-padded tails) ---
    auto loadA = [&](int k0) {
#pragma unroll
        for (int c = 0; c < 4; c++) {
            const int kg = k0 + aKc + c * 4;
            float4 v = make_float4(0.f, 0.f, 0.f, 0.f);
            if (kg < K1p) {
                if (kg < K1) v = *(const float4*)(A1 + (long)(m0 + aRow) * lda1 + kg);
            } else {
                const int ks = kg - K1p;
                if (ks < K2) v = *(const float4*)(A2 + (long)(m0 + aRow) * lda2 + ks);
            }
            a_st[c] = v;
        }
    };
    auto loadW = [&](int k0) {
        const int col = n0 + wCol;
#pragma unroll
        for (int h = 0; h < 4; h++) {
            const int kg = k0 + wRow + h * 8;
            float4 v = make_float4(0.f, 0.f, 0.f, 0.f);
            if (col < N) {   // N % 4 == 0 for all our shapes
                if (kg < K1p) {
                    if (kg < K1) v = *(const float4*)(W1 + (long)kg * ldw1 + col);
                } else {
                    const int ks = kg - K1p;
                    if (ks < K2) v = *(const float4*)(W2 + (long)ks * ldw2 + col);
                }
            }
            w_st[h] = v;
        }
    };

    float acc[4][4][4];
#pragma unroll
    for (int i = 0; i < 4; i++)
#pragma unroll
        for (int j = 0; j < 4; j++)
#pragma unroll
            for (int r = 0; r < 4; r++) acc[i][j][r] = 0.f;

    loadA(0);
    loadW(0);

    for (int k0 = 0; k0 < Ktot; k0 += 32) {
        // commit staged tile to smem (tf32-rounded)
#pragma unroll
        for (int c = 0; c < 4; c++) {
            uint4 u = { f2tf(a_st[c].x), f2tf(a_st[c].y), f2tf(a_st[c].z), f2tf(a_st[c].w) };
            *(uint4*)&As[aRow][aKc + c * 4] = u;
        }
#pragma unroll
        for (int h = 0; h < 4; h++) {
            uint4 u = { f2tf(w_st[h].x), f2tf(w_st[h].y), f2tf(w_st[h].z), f2tf(w_st[h].w) };
            *(uint4*)&Ws[wRow + h * 8][wCol] = u;
        }
        __syncthreads();

        // prefetch next tile while computing this one
        if (k0 + 32 < Ktot) { loadA(k0 + 32); loadW(k0 + 32); }

#pragma unroll
        for (int ks = 0; ks < 32; ks += 8) {
            uint32_t af[4][4], bf[4][2];
#pragma unroll
            for (int i = 0; i < 4; i++) {
                const int mb = warp_m + i * 16 + g;
                af[i][0] = As[mb    ][ks + qd];
                af[i][1] = As[mb + 8][ks + qd];
                af[i][2] = As[mb    ][ks + qd + 4];
                af[i][3] = As[mb + 8][ks + qd + 4];
            }
#pragma unroll
            for (int j = 0; j < 4; j++) {
                const int nb = warp_n + j * 8 + g;
                bf[j][0] = Ws[ks + qd    ][nb];
                bf[j][1] = Ws[ks + qd + 4][nb];
            }
#pragma unroll
            for (int i = 0; i < 4; i++)
#pragma unroll
                for (int j = 0; j < 4; j++)
                    mma_tf32(acc[i][j], af[i], bf[j], acc[i][j]);
        }
        __syncthreads();
    }

    // ---- epilogue ----
#pragma unroll
    for (int i = 0; i < 4; i++) {
        const long mA = m0 + warp_m + i * 16 + g;
        const long mB = mA + 8;
#pragma unroll
        for (int j = 0; j < 4; j++) {
            const int n = n0 + warp_n + j * 8 + qd * 2;
#pragma unroll
            for (int e = 0; e < 2; e++) {
                const int col = n + e;
                if (col < N) {
                    float vA = acc[i][j][e];
                    float vB = acc[i][j][2 + e];
                    if (bias) { vA += bias[col]; vB += bias[col]; }
                    C[mA * ldc + col] = vA;
                    C[mB * ldc + col] = vB;
                }
            }
        }
    }
}

// ---------------- input attention + top-k mask + rnn_in ------------------------
__global__ void __launch_bounds__(128) attn_kernel(const float* __restrict__ kb,
                                                   const float* __restrict__ vb)
{
    const int b = blockIdx.x;
    const int t = threadIdx.x;
    __shared__ float sq[NRIM * 128], skx[128], skb[128];
    __shared__ float s2[12], sm[NRIM], sp0[NRIM], sp1[NRIM];

    for (int i = t; i < NRIM * 128; i += 128) sq[i] = g_q[b * NRIM * 128 + i];
    if (t < 128) { skx[t] = g_kx[b * 128 + t]; skb[t] = kb[t]; }
    __syncthreads();

    const int w = t >> 5, lane = t & 31;
    for (int d = w; d < 12; d += 4) {
        const int n = d >> 1, m = d & 1;
        const float* kv = m ? skb : skx;
        float s = 0.f;
        for (int k = lane; k < 128; k += 32) s += sq[n * 128 + k] * kv[k];
#pragma unroll
        for (int o = 16; o; o >>= 1) s += __shfl_xor_sync(0xffffffffu, s, o);
        if (!lane) s2[d] = s * (1.0f / 16.0f);
    }
    __syncthreads();

    if (t < NRIM) {
        const int n = t;
        const float sn = s2[n * 2];
        int rank = 0;
        for (int m2 = 0; m2 < NRIM; m2++) {
            const float sv = s2[m2 * 2];
            if (sv > sn || (sv == sn && m2 < n)) rank++;
        }
        const float mk = (rank < TOPK) ? 1.0f : 0.0f;
        sm[n] = mk;
        g_mask[b * NRIM + n] = mk;
        const float a0 = s2[n * 2], a1 = s2[n * 2 + 1];
        const float mx = fmaxf(a0, a1);
        const float e0 = expf(a0 - mx), e1 = expf(a1 - mx);
        const float inv = 1.0f / (e0 + e1);
        sp0[n] = e0 * inv;
        sp1[n] = e1 * inv;
    }
    __syncthreads();

    for (int v = t; v < IVS; v += 128) {
        const float v20 = 0.5f * (g_vx[b * 800 + v] + g_vx[b * 800 + 400 + v]);
        const float v21 = 0.5f * (vb[v] + vb[400 + v]);
#pragma unroll
        for (int n = 0; n < NRIM; n++)
            g_rnn[(b * NRIM + n) * IVS + v] = sm[n] * (sp0[n] * v20 + sp1[n] * v21);
    }
}

// ---------------- LSTM pointwise -----------------------------------------------
__global__ void lstm_kernel(const float* __restrict__ cs, float* __restrict__ out)
{
    const int i = blockIdx.x * blockDim.x + threadIdx.x;
    if (i >= BF) return;
    const int bn = i >> 8;
    const int u  = i & 255;
    const float* p = g_pre + (long)bn * 1024;
    const float nc = tanhf(p[u]);
    const float ig = 1.f / (1.f + expf(-p[256 + u]));
    const float fg = 1.f / (1.f + expf(-p[512 + u]));
    const float og = 1.f / (1.f + expf(-p[768 + u]));
    const float c  = cs[i] * fg + ig * nc;
    const float h  = og * tanhf(c);
    g_hnew[i] = h;
    const float m = g_mask[bn];
    out[2L * BF + i] = (m != 0.f) ? c : cs[i];
}

// ---------------- communication attention --------------------------------------
__global__ void __launch_bounds__(128) cattn_kernel()
{
    const int b = blockIdx.x;
    const int t = threadIdx.x;
    __shared__ float sk[NRIM * 128], sq[NRIM * 128], sv[NRIM * 400];
    __shared__ float sm[NRIM], sc[144], sp[144];

    for (int i = t; i < NRIM * 128; i += 128) {
        sk[i] = g_ck[b * NRIM * 128 + i];
        sq[i] = g_cq[b * NRIM * 128 + i];
    }
    for (int i = t; i < NRIM * 400; i += 128) sv[i] = g_cv[b * NRIM * 400 + i];
    if (t < NRIM) sm[t] = g_mask[b * NRIM + t];
    __syncthreads();

    for (int d = t; d < 144; d += 128) {
        const int h = d / 36, r = d % 36, n = r / 6, m = r % 6;
        float s = 0.f;
#pragma unroll
        for (int k = 0; k < CKS; k++)
            s += sq[n * 128 + h * CKS + k] * sk[m * 128 + h * CKS + k];
        sc[d] = s * 0.17677669529663687f;
    }
    __syncthreads();

    if (t < 24) {
        const int h = t / 6, n = t % 6;
        float mx = -1e30f;
        for (int m = 0; m < 6; m++) mx = fmaxf(mx, sc[h * 36 + n * 6 + m]);
        float e[6], sum = 0.f;
        for (int m = 0; m < 6; m++) { e[m] = expf(sc[h * 36 + n * 6 + m] - mx); sum += e[m]; }
        const float inv = sm[n] / sum;
        for (int m = 0; m < 6; m++) sp[h * 36 + n * 6 + m] = e[m] * inv;
    }
    __syncthreads();

    for (int idx = t; idx < NRIM * 400; idx += 128) {
        const int n = idx / 400, r = idx % 400, h = r / 100;
        float a = 0.f;
#pragma unroll
        for (int m = 0; m < 6; m++) a += sp[h * 36 + n * 6 + m] * sv[m * 400 + r];
        g_ctx[b * NRIM * 400 + idx] = a;
    }
}

// ---------------- final h update ------------------------------------------------
__global__ void final_kernel(const float* __restrict__ hs, float* __restrict__ out)
{
    const int i = blockIdx.x * blockDim.x + threadIdx.x;
    if (i >= BF) return;
    const int bn = i >> 8;
    const float m = g_mask[bn];
    const float h = (m != 0.f) ? (g_hcm[i] + g_hnew[i]) : hs[i];
    out[i]      = h;
    out[BF + i] = h;
}

// -------------------------------------------------------------------------------
extern "C" void kernel_launch(void* const* d_in, const int* in_sizes, int n_in,
                              void* d_out, int out_size)
{
    const float* x     = (const float*)d_in[0];
    const float* hs    = (const float*)d_in[1];
    const float* cs    = (const float*)d_in[2];
    const float* keyW  = (const float*)d_in[3];
    const float* keyb  = (const float*)d_in[4];
    const float* valW  = (const float*)d_in[5];
    const float* valb  = (const float*)d_in[6];
    const float* qW    = (const float*)d_in[7];
    const float* i2h   = (const float*)d_in[8];
    const float* h2h   = (const float*)d_in[9];
    const float* WkC   = (const float*)d_in[10];
    const float* WvC   = (const float*)d_in[11];
    const float* WqC   = (const float*)d_in[12];
    const float* WoC   = (const float*)d_in[13];
    float* out = (float*)d_out;

    float *kx, *vx, *q, *rnn, *pre, *ck, *cv, *cq, *ctx, *hcm, *hnew;
    cudaGetSymbolAddress((void**)&kx,  g_kx);
    cudaGetSymbolAddress((void**)&vx,  g_vx);
    cudaGetSymbolAddress((void**)&q,   g_q);
    cudaGetSymbolAddress((void**)&rnn, g_rnn);
    cudaGetSymbolAddress((void**)&pre, g_pre);
    cudaGetSymbolAddress((void**)&ck,  g_ck);
    cudaGetSymbolAddress((void**)&cv,  g_cv);
    cudaGetSymbolAddress((void**)&cq,  g_cq);
    cudaGetSymbolAddress((void**)&ctx, g_ctx);
    cudaGetSymbolAddress((void**)&hcm, g_hcm);
    cudaGetSymbolAddress((void**)&hnew, g_hnew);

    const dim3 blk(256);

    // 1) kx = x @ key_W + key_b  (fp32: feeds top-k signal)
    gemm128<<<dim3(1, 64, 1), blk>>>(x, keyW, keyb, kx, 128, 512, 512, 128, 128, 0, 0, 0, 0);
    // 2) vx = x @ value_W + value_b  (tf32 v2)
    gemm_tf32_v2<<<dim3(7, 64, 1), blk>>>(x, valW, 512, 512, 800,
                                          x, valW, 0, 512, 800,
                                          valb, vx, 800, 800, 0, 0, 0, 0, 0);
    // 3) q = hs @ query_W[n]  (fp32: feeds top-k signal)
    gemm128<<<dim3(1, 64, NRIM), blk>>>(hs, qW, nullptr, q, 128, 256, NRIM * UNITS, 128,
                                        NRIM * 128, UNITS, 256L * 128, 128, 0);
    // 4) input attention + top-k + rnn_in
    attn_kernel<<<BSZ, 128>>>(keyb, valb);
    // 5+6) preact = rnn_in @ i2h[n] + hs @ h2h[n]   (fused dual-K tf32 v2)
    gemm_tf32_v2<<<dim3(8, 64, NRIM), blk>>>(rnn, i2h, IVS,   NRIM * IVS,   1024,
                                             hs,  h2h, UNITS, NRIM * UNITS, 1024,
                                             nullptr, pre, 1024, NRIM * 1024,
                                             IVS, (long)IVS * 1024,
                                             UNITS, (long)UNITS * 1024,
                                             1024);
    // 7) LSTM pointwise
    lstm_kernel<<<(BF + 255) / 256, 256>>>(cs, out);
    // 8) ck/cv/cq = h_new @ W*_comm[n]  (tf32 v2)
    gemm_tf32_v2<<<dim3(1, 64, NRIM), blk>>>(hnew, WkC, UNITS, NRIM * UNITS, 128,
                                             hnew, WkC, 0, NRIM * UNITS, 128,
                                             nullptr, ck, 128, NRIM * 128,
                                             UNITS, 256L * 128, 0, 0, 128);
    gemm_tf32_v2<<<dim3(4, 64, NRIM), blk>>>(hnew, WvC, UNITS, NRIM * UNITS, 400,
                                             hnew, WvC, 0, NRIM * UNITS, 400,
                                             nullptr, cv, 400, NRIM * 400,
                                             UNITS, 256L * 400, 0, 0, 400);
    gemm_tf32_v2<<<dim3(1, 64, NRIM), blk>>>(hnew, WqC, UNITS, NRIM * UNITS, 128,
                                             hnew, WqC, 0, NRIM * UNITS, 128,
                                             nullptr, cq, 128, NRIM * 128,
                                             UNITS, 256L * 128, 0, 0, 128);
    // 9) communication attention -> ctx
    cattn_kernel<<<BSZ, 128>>>();
    // 10) hcm = ctx @ Wout_comm[n]  (tf32 v2)
    gemm_tf32_v2<<<dim3(2, 64, NRIM), blk>>>(ctx, WoC, 400, NRIM * 400, 256,
                                             ctx, WoC, 0, NRIM * 400, 256,
                                             nullptr, hcm, 256, NRIM * UNITS,
                                             400, 400L * 256, 0, 0, 256);
    // 11) final h update
    final_kernel<<<(BF + 255) / 256, 256>>>(hs, out);
}

// round 6
// speedup vs baseline: 3.0051x; 1.3584x over previous
#include <cuda_runtime.h>
#include <cuda_fp16.h>
#include <math.h>
#include <stdint.h>
#include <string.h>

#define BSZ   8192
#define DD    512
#define UNITS 256
#define NRIM  6
#define TOPK  4
#define NIH   2
#define IKS   64
#define IVS   400
#define NCH   4
#define CKS   32
#define CVS   100

#define BF (BSZ*NRIM*UNITS)

// ---------------- scratch ------------------------------------------------------
__device__ float g_kx  [BSZ*128];
__device__ float g_vx  [BSZ*800];
__device__ float g_q   [BSZ*NRIM*128];
__device__ float g_mask[BSZ*NRIM];
__device__ float g_rnn [BSZ*NRIM*IVS];
__device__ float g_pre [BSZ*NRIM*1024];
__device__ float g_hnew[BSZ*NRIM*UNITS];
__device__ float g_ck  [BSZ*NRIM*128];
__device__ float g_cv  [BSZ*NRIM*400];
__device__ float g_cq  [BSZ*NRIM*128];
__device__ float g_ctx [BSZ*NRIM*400];
__device__ float g_hcm [BSZ*NRIM*UNITS];
// packed half2 weights, layout [k/2][Npad], zero-padded
__device__ uint32_t g_wh_val[256*896];
__device__ uint32_t g_wh_pre[6*336*1024];
__device__ uint32_t g_wh_k  [6*128*128];
__device__ uint32_t g_wh_q  [6*128*128];
__device__ uint32_t g_wh_v  [6*128*512];
__device__ uint32_t g_wh_o  [6*208*256];

// ---------------- weight pack: Wh[k2][n] = half2(W(2k2,n), W(2k2+1,n)) --------
__global__ void pack_w(const float* __restrict__ W1, int K1, int ldw1, long sW1,
                       const float* __restrict__ W2, int K2, int ldw2, long sW2,
                       uint32_t* __restrict__ Wh, int N, int Npad, int Ktot, long sWh)
{
    const int z = blockIdx.z;
    const long idx = (long)blockIdx.x * 256 + threadIdx.x;
    const int rows = Ktot / 2;
    if (idx >= (long)rows * Npad) return;
    const int k2 = (int)(idx / Npad);
    const int n  = (int)(idx % Npad);
    const int K1p = (K1 + 31) & ~31;

    float v[2];
#pragma unroll
    for (int e = 0; e < 2; e++) {
        const int k = 2 * k2 + e;
        float x = 0.f;
        if (n < N) {
            if (k < K1p) { if (k < K1) x = W1[(long)z * sW1 + (long)k * ldw1 + n]; }
            else { const int ks = k - K1p; if (ks < K2) x = W2[(long)z * sW2 + (long)ks * ldw2 + n]; }
        }
        v[e] = x;
    }
    __half2 h = __float22half2_rn(make_float2(v[0], v[1]));
    uint32_t u; memcpy(&u, &h, 4);
    Wh[(long)z * sWh + idx] = u;
}

// =================== fp16 tensor-core GEMM ====================================
// C[M x N] = A1[M x K1](pad32) ++K A2[M x K2](pad32)  times  Wh (packed half2),
// tile 128x128, BK=32, 8 warps (2Mx4N), warp tile 64x32, mma.m16n8k16,
// register-staged double buffering. fp32 accumulate.
__device__ __forceinline__ void mma_fp16(float* d, const uint32_t* a, const uint32_t* b) {
    asm volatile(
        "mma.sync.aligned.m16n8k16.row.col.f32.f16.f16.f32 "
        "{%0,%1,%2,%3}, {%4,%5,%6,%7}, {%8,%9}, {%0,%1,%2,%3};\n"
        : "+f"(d[0]), "+f"(d[1]), "+f"(d[2]), "+f"(d[3])
        : "r"(a[0]), "r"(a[1]), "r"(a[2]), "r"(a[3]),
          "r"(b[0]), "r"(b[1]));
}

__global__ void __launch_bounds__(256) gemm_fp16(
    const float* __restrict__ A1, int K1, int lda1, long sA1,
    const float* __restrict__ A2, int K2, int lda2, long sA2,
    const uint32_t* __restrict__ Wh, int ldwh, long sWh, int Ktot,
    const float* __restrict__ bias, float* __restrict__ C, int N, int ldc, long sC)
{
    __shared__ uint32_t As[128][20];   // [m][k2], 16 half2 + pad4 -> frag reads conflict-free
    __shared__ uint32_t Ws[16][136];   // [k2][n], pad 136 -> frag reads conflict-free

    const int tid = threadIdx.x, wid = tid >> 5, lane = tid & 31;
    const int warp_m = (wid & 1) * 64, warp_n = (wid >> 1) * 32;
    const int g = lane >> 2, qd = lane & 3;
    const int m0 = blockIdx.y * 128, n0 = blockIdx.x * 128, z = blockIdx.z;
    A1 += (long)z * sA1;
    if (A2) A2 += (long)z * sA2;
    Wh += (long)z * sWh;
    C  += (long)z * sC;
    const int K1p = (K1 + 31) & ~31;

    const int aRow = tid >> 3;   // + c*32
    const int aCh  = tid & 7;    // float4 chunk within BK=32

    float4   a_st[4];
    uint32_t w_st[8];

    auto loadA = [&](int kg0) {
        const int kg = kg0 + aCh * 4;
#pragma unroll
        for (int c = 0; c < 4; c++) {
            const int row = aRow + c * 32;
            float4 v = make_float4(0.f, 0.f, 0.f, 0.f);
            if (kg < K1p) { if (kg < K1) v = *(const float4*)(A1 + (long)(m0 + row) * lda1 + kg); }
            else { const int ks = kg - K1p; if (ks < K2) v = *(const float4*)(A2 + (long)(m0 + row) * lda2 + ks); }
            a_st[c] = v;
        }
    };
    auto loadW = [&](int kg0) {
        const int r0 = kg0 >> 1;
#pragma unroll
        for (int i = 0; i < 8; i++) {
            const int idx = i * 256 + tid;
            w_st[i] = Wh[(long)(r0 + (idx >> 7)) * ldwh + n0 + (idx & 127)];
        }
    };
    auto commit = [&]() {
#pragma unroll
        for (int c = 0; c < 4; c++) {
            const int row = aRow + c * 32;
            __half2 h0 = __float22half2_rn(make_float2(a_st[c].x, a_st[c].y));
            __half2 h1 = __float22half2_rn(make_float2(a_st[c].z, a_st[c].w));
            uint32_t u0, u1;
            memcpy(&u0, &h0, 4);
            memcpy(&u1, &h1, 4);
            As[row][aCh * 2]     = u0;
            As[row][aCh * 2 + 1] = u1;
        }
#pragma unroll
        for (int i = 0; i < 8; i++) {
            const int idx = i * 256 + tid;
            Ws[idx >> 7][idx & 127] = w_st[i];
        }
    };

    float acc[4][4][4];
#pragma unroll
    for (int i = 0; i < 4; i++)
#pragma unroll
        for (int j = 0; j < 4; j++)
#pragma unroll
            for (int r = 0; r < 4; r++) acc[i][j][r] = 0.f;

    loadA(0);
    loadW(0);

    const int T = Ktot / 32;
    for (int t = 0; t < T; t++) {
        commit();
        __syncthreads();
        if (t + 1 < T) { loadA((t + 1) * 32); loadW((t + 1) * 32); }

#pragma unroll
        for (int ks2 = 0; ks2 < 2; ks2++) {
            const int kb = ks2 * 8;
            uint32_t af[4][4], bf[4][2];
#pragma unroll
            for (int i = 0; i < 4; i++) {
                const int mb = warp_m + i * 16 + g;
                af[i][0] = As[mb    ][kb + qd];
                af[i][1] = As[mb + 8][kb + qd];
                af[i][2] = As[mb    ][kb + qd + 4];
                af[i][3] = As[mb + 8][kb + qd + 4];
            }
#pragma unroll
            for (int j = 0; j < 4; j++) {
                const int nb = warp_n + j * 8 + g;
                bf[j][0] = Ws[kb + qd    ][nb];
                bf[j][1] = Ws[kb + qd + 4][nb];
            }
#pragma unroll
            for (int i = 0; i < 4; i++)
#pragma unroll
                for (int j = 0; j < 4; j++)
                    mma_fp16(acc[i][j], af[i], bf[j]);
        }
        __syncthreads();
    }

    // ---- epilogue ----
#pragma unroll
    for (int i = 0; i < 4; i++) {
        const long mA = m0 + warp_m + i * 16 + g;
        const long mB = mA + 8;
#pragma unroll
        for (int j = 0; j < 4; j++) {
            const int n = n0 + warp_n + j * 8 + qd * 2;
#pragma unroll
            for (int e = 0; e < 2; e++) {
                const int col = n + e;
                if (col < N) {
                    float vA = acc[i][j][e];
                    float vB = acc[i][j][2 + e];
                    if (bias) { vA += bias[col]; vB += bias[col]; }
                    C[mA * ldc + col] = vA;
                    C[mB * ldc + col] = vB;
                }
            }
        }
    }
}

// =================== fp32 GEMM (top-k-sensitive path only) ====================
__global__ void __launch_bounds__(256) gemm128(
    const float* __restrict__ A, const float* __restrict__ W,
    const float* __restrict__ bias, float* __restrict__ C,
    int N, int Kd, int lda, int ldw, int ldc,
    long sA, long sW, long sC, int accum)
{
    A += (long)blockIdx.z * sA;
    W += (long)blockIdx.z * sW;
    C += (long)blockIdx.z * sC;

    __shared__ float As[8][128];
    __shared__ float Ws[8][128];

    const int tid = threadIdx.x;
    const int m0  = blockIdx.y * 128;
    const int n0  = blockIdx.x * 128;

    const int aRow = tid >> 1;
    const int aK   = (tid & 1) * 4;
    const int wK   = tid >> 5;
    const int wC   = (tid & 31) * 4;
    const int ty   = tid >> 4;
    const int tx   = tid & 15;

    float acc[8][8];
#pragma unroll
    for (int i = 0; i < 8; i++)
#pragma unroll
        for (int j = 0; j < 8; j++) acc[i][j] = 0.f;

    const float* Aptr = A + (long)(m0 + aRow) * lda + aK;

    for (int k0 = 0; k0 < Kd; k0 += 8) {
        float4 av = *(const float4*)(Aptr + k0);
        As[aK + 0][aRow] = av.x;
        As[aK + 1][aRow] = av.y;
        As[aK + 2][aRow] = av.z;
        As[aK + 3][aRow] = av.w;
        {
            const int col = n0 + wC;
            const float* wp = W + (long)(k0 + wK) * ldw;
            if (col + 3 < N) {
                *(float4*)&Ws[wK][wC] = *(const float4*)(wp + col);
            } else {
#pragma unroll
                for (int j = 0; j < 4; j++)
                    Ws[wK][wC + j] = (col + j < N) ? wp[col + j] : 0.f;
            }
        }
        __syncthreads();

#pragma unroll
        for (int kk = 0; kk < 8; kk++) {
            float a[8], bq[8];
            *(float4*)(a)      = *(const float4*)&As[kk][ty * 8];
            *(float4*)(a + 4)  = *(const float4*)&As[kk][ty * 8 + 4];
            *(float4*)(bq)     = *(const float4*)&Ws[kk][tx * 8];
            *(float4*)(bq + 4) = *(const float4*)&Ws[kk][tx * 8 + 4];
#pragma unroll
            for (int i = 0; i < 8; i++)
#pragma unroll
                for (int j = 0; j < 8; j++)
                    acc[i][j] += a[i] * bq[j];
        }
        __syncthreads();
    }

#pragma unroll
    for (int i = 0; i < 8; i++) {
        const long row = m0 + ty * 8 + i;
#pragma unroll
        for (int j = 0; j < 8; j++) {
            const int col = n0 + tx * 8 + j;
            if (col < N) {
                float v = acc[i][j];
                if (bias)  v += bias[col];
                if (accum) v += C[row * ldc + col];
                C[row * ldc + col] = v;
            }
        }
    }
}

// ---------------- input attention + top-k mask + rnn_in ------------------------
__global__ void __launch_bounds__(128) attn_kernel(const float* __restrict__ kb,
                                                   const float* __restrict__ vb)
{
    const int b = blockIdx.x;
    const int t = threadIdx.x;
    __shared__ float sq[NRIM * 128], skx[128], skb[128];
    __shared__ float s2[12], sm[NRIM], sp0[NRIM], sp1[NRIM];

    for (int i = t; i < NRIM * 128; i += 128) sq[i] = g_q[b * NRIM * 128 + i];
    if (t < 128) { skx[t] = g_kx[b * 128 + t]; skb[t] = kb[t]; }
    __syncthreads();

    const int w = t >> 5, lane = t & 31;
    for (int d = w; d < 12; d += 4) {
        const int n = d >> 1, m = d & 1;
        const float* kv = m ? skb : skx;
        float s = 0.f;
        for (int k = lane; k < 128; k += 32) s += sq[n * 128 + k] * kv[k];
#pragma unroll
        for (int o = 16; o; o >>= 1) s += __shfl_xor_sync(0xffffffffu, s, o);
        if (!lane) s2[d] = s * (1.0f / 16.0f);
    }
    __syncthreads();

    if (t < NRIM) {
        const int n = t;
        const float sn = s2[n * 2];
        int rank = 0;
        for (int m2 = 0; m2 < NRIM; m2++) {
            const float sv = s2[m2 * 2];
            if (sv > sn || (sv == sn && m2 < n)) rank++;
        }
        const float mk = (rank < TOPK) ? 1.0f : 0.0f;
        sm[n] = mk;
        g_mask[b * NRIM + n] = mk;
        const float a0 = s2[n * 2], a1 = s2[n * 2 + 1];
        const float mx = fmaxf(a0, a1);
        const float e0 = expf(a0 - mx), e1 = expf(a1 - mx);
        const float inv = 1.0f / (e0 + e1);
        sp0[n] = e0 * inv;
        sp1[n] = e1 * inv;
    }
    __syncthreads();

    for (int v = t; v < IVS; v += 128) {
        const float v20 = 0.5f * (g_vx[b * 800 + v] + g_vx[b * 800 + 400 + v]);
        const float v21 = 0.5f * (vb[v] + vb[400 + v]);
#pragma unroll
        for (int n = 0; n < NRIM; n++)
            g_rnn[(b * NRIM + n) * IVS + v] = sm[n] * (sp0[n] * v20 + sp1[n] * v21);
    }
}

// ---------------- LSTM pointwise -----------------------------------------------
__global__ void lstm_kernel(const float* __restrict__ cs, float* __restrict__ out)
{
    const int i = blockIdx.x * blockDim.x + threadIdx.x;
    if (i >= BF) return;
    const int bn = i >> 8;
    const int u  = i & 255;
    const float* p = g_pre + (long)bn * 1024;
    const float nc = tanhf(p[u]);
    const float ig = 1.f / (1.f + expf(-p[256 + u]));
    const float fg = 1.f / (1.f + expf(-p[512 + u]));
    const float og = 1.f / (1.f + expf(-p[768 + u]));
    const float c  = cs[i] * fg + ig * nc;
    const float h  = og * tanhf(c);
    g_hnew[i] = h;
    const float m = g_mask[bn];
    out[2L * BF + i] = (m != 0.f) ? c : cs[i];
}

// ---------------- communication attention --------------------------------------
__global__ void __launch_bounds__(128) cattn_kernel()
{
    const int b = blockIdx.x;
    const int t = threadIdx.x;
    __shared__ float sk[NRIM * 128], sq[NRIM * 128], sv[NRIM * 400];
    __shared__ float sm[NRIM], sc[144], sp[144];

    for (int i = t; i < NRIM * 128; i += 128) {
        sk[i] = g_ck[b * NRIM * 128 + i];
        sq[i] = g_cq[b * NRIM * 128 + i];
    }
    for (int i = t; i < NRIM * 400; i += 128) sv[i] = g_cv[b * NRIM * 400 + i];
    if (t < NRIM) sm[t] = g_mask[b * NRIM + t];
    __syncthreads();

    for (int d = t; d < 144; d += 128) {
        const int h = d / 36, r = d % 36, n = r / 6, m = r % 6;
        float s = 0.f;
#pragma unroll
        for (int k = 0; k < CKS; k++)
            s += sq[n * 128 + h * CKS + k] * sk[m * 128 + h * CKS + k];
        sc[d] = s * 0.17677669529663687f;
    }
    __syncthreads();

    if (t < 24) {
        const int h = t / 6, n = t % 6;
        float mx = -1e30f;
        for (int m = 0; m < 6; m++) mx = fmaxf(mx, sc[h * 36 + n * 6 + m]);
        float e[6], sum = 0.f;
        for (int m = 0; m < 6; m++) { e[m] = expf(sc[h * 36 + n * 6 + m] - mx); sum += e[m]; }
        const float inv = sm[n] / sum;
        for (int m = 0; m < 6; m++) sp[h * 36 + n * 6 + m] = e[m] * inv;
    }
    __syncthreads();

    for (int idx = t; idx < NRIM * 400; idx += 128) {
        const int n = idx / 400, r = idx % 400, h = r / 100;
        float a = 0.f;
#pragma unroll
        for (int m = 0; m < 6; m++) a += sp[h * 36 + n * 6 + m] * sv[m * 400 + r];
        g_ctx[b * NRIM * 400 + idx] = a;
    }
}

// ---------------- final h update ------------------------------------------------
__global__ void final_kernel(const float* __restrict__ hs, float* __restrict__ out)
{
    const int i = blockIdx.x * blockDim.x + threadIdx.x;
    if (i >= BF) return;
    const int bn = i >> 8;
    const float m = g_mask[bn];
    const float h = (m != 0.f) ? (g_hcm[i] + g_hnew[i]) : hs[i];
    out[i]      = h;
    out[BF + i] = h;
}

// -------------------------------------------------------------------------------
extern "C" void kernel_launch(void* const* d_in, const int* in_sizes, int n_in,
                              void* d_out, int out_size)
{
    const float* x     = (const float*)d_in[0];
    const float* hs    = (const float*)d_in[1];
    const float* cs    = (const float*)d_in[2];
    const float* keyW  = (const float*)d_in[3];
    const float* keyb  = (const float*)d_in[4];
    const float* valW  = (const float*)d_in[5];
    const float* valb  = (const float*)d_in[6];
    const float* qW    = (const float*)d_in[7];
    const float* i2h   = (const float*)d_in[8];
    const float* h2h   = (const float*)d_in[9];
    const float* WkC   = (const float*)d_in[10];
    const float* WvC   = (const float*)d_in[11];
    const float* WqC   = (const float*)d_in[12];
    const float* WoC   = (const float*)d_in[13];
    float* out = (float*)d_out;

    float *kx, *vx, *q, *rnn, *pre, *ck, *cv, *cq, *ctx, *hcm, *hnew;
    uint32_t *wh_val, *wh_pre, *wh_k, *wh_q, *wh_v, *wh_o;
    cudaGetSymbolAddress((void**)&kx,  g_kx);
    cudaGetSymbolAddress((void**)&vx,  g_vx);
    cudaGetSymbolAddress((void**)&q,   g_q);
    cudaGetSymbolAddress((void**)&rnn, g_rnn);
    cudaGetSymbolAddress((void**)&pre, g_pre);
    cudaGetSymbolAddress((void**)&ck,  g_ck);
    cudaGetSymbolAddress((void**)&cv,  g_cv);
    cudaGetSymbolAddress((void**)&cq,  g_cq);
    cudaGetSymbolAddress((void**)&ctx, g_ctx);
    cudaGetSymbolAddress((void**)&hcm, g_hcm);
    cudaGetSymbolAddress((void**)&hnew, g_hnew);
    cudaGetSymbolAddress((void**)&wh_val, g_wh_val);
    cudaGetSymbolAddress((void**)&wh_pre, g_wh_pre);
    cudaGetSymbolAddress((void**)&wh_k, g_wh_k);
    cudaGetSymbolAddress((void**)&wh_q, g_wh_q);
    cudaGetSymbolAddress((void**)&wh_v, g_wh_v);
    cudaGetSymbolAddress((void**)&wh_o, g_wh_o);

    // ---- weight packs (fp32 -> half2 k-pairs, zero-padded) ----
    pack_w<<<896, 256>>>(valW, 512, 800, 0, nullptr, 0, 0, 0,
                         wh_val, 800, 896, 512, 0);
    pack_w<<<dim3(1344, 1, NRIM), 256>>>(i2h, 400, 1024, 400L * 1024,
                                         h2h, 256, 1024, 256L * 1024,
                                         wh_pre, 1024, 1024, 672, 336L * 1024);
    pack_w<<<dim3(64, 1, NRIM), 256>>>(WkC, 256, 128, 256L * 128, nullptr, 0, 0, 0,
                                       wh_k, 128, 128, 256, 128L * 128);
    pack_w<<<dim3(64, 1, NRIM), 256>>>(WqC, 256, 128, 256L * 128, nullptr, 0, 0, 0,
                                       wh_q, 128, 128, 256, 128L * 128);
    pack_w<<<dim3(256, 1, NRIM), 256>>>(WvC, 256, 400, 256L * 400, nullptr, 0, 0, 0,
                                        wh_v, 400, 512, 256, 128L * 512);
    pack_w<<<dim3(208, 1, NRIM), 256>>>(WoC, 400, 256, 400L * 256, nullptr, 0, 0, 0,
                                        wh_o, 256, 256, 416, 208L * 256);

    // 1) kx = x @ key_W + key_b  (fp32: feeds top-k signal)
    gemm128<<<dim3(1, 64, 1), 256>>>(x, keyW, keyb, kx, 128, 512, 512, 128, 128, 0, 0, 0, 0);
    // 2) vx = x @ value_W + value_b  (fp16 tensor)
    gemm_fp16<<<dim3(7, 64, 1), 256>>>(x, 512, 512, 0, nullptr, 0, 0, 0,
                                       wh_val, 896, 0, 512, valb, vx, 800, 800, 0);
    // 3) q = hs @ query_W[n]  (fp32: feeds top-k signal)
    gemm128<<<dim3(1, 64, NRIM), 256>>>(hs, qW, nullptr, q, 128, 256, NRIM * UNITS, 128,
                                        NRIM * 128, UNITS, 256L * 128, 128, 0);
    // 4) input attention + top-k + rnn_in
    attn_kernel<<<BSZ, 128>>>(keyb, valb);
    // 5+6) preact = rnn_in @ i2h[n] + hs @ h2h[n]  (fused dual-K fp16 tensor)
    gemm_fp16<<<dim3(8, 64, NRIM), 256>>>(rnn, 400, NRIM * IVS, IVS,
                                          hs, 256, NRIM * UNITS, UNITS,
                                          wh_pre, 1024, 336L * 1024, 672,
                                          nullptr, pre, 1024, NRIM * 1024, 1024);
    // 7) LSTM pointwise
    lstm_kernel<<<(BF + 255) / 256, 256>>>(cs, out);
    // 8) ck/cv/cq = h_new @ W*_comm[n]  (fp16 tensor)
    gemm_fp16<<<dim3(1, 64, NRIM), 256>>>(hnew, 256, NRIM * UNITS, UNITS,
                                          nullptr, 0, 0, 0,
                                          wh_k, 128, 128L * 128, 256,
                                          nullptr, ck, 128, NRIM * 128, 128);
    gemm_fp16<<<dim3(4, 64, NRIM), 256>>>(hnew, 256, NRIM * UNITS, UNITS,
                                          nullptr, 0, 0, 0,
                                          wh_v, 512, 128L * 512, 256,
                                          nullptr, cv, 400, NRIM * 400, 400);
    gemm_fp16<<<dim3(1, 64, NRIM), 256>>>(hnew, 256, NRIM * UNITS, UNITS,
                                          nullptr, 0, 0, 0,
                                          wh_q, 128, 128L * 128, 256,
                                          nullptr, cq, 128, NRIM * 128, 128);
    // 9) communication attention -> ctx
    cattn_kernel<<<BSZ, 128>>>();
    // 10) hcm = ctx @ Wout_comm[n]  (fp16 tensor)
    gemm_fp16<<<dim3(2, 64, NRIM), 256>>>(ctx, 400, NRIM * IVS, IVS,
                                          nullptr, 0, 0, 0,
                                          wh_o, 256, 208L * 256, 416,
                                          nullptr, hcm, 256, NRIM * UNITS, 256);
    // 11) final h update
    final_kernel<<<(BF + 255) / 256, 256>>>(hs, out);
}